// round 1
// baseline (speedup 1.0000x reference)
#include <cuda_runtime.h>
#include <math.h>

#define NN 4
#define CC 26
#define NC 104
#define HH 512
#define WW 512
#define PH 171
#define PW 171
#define NY 169
#define NX 169
#define MTOT (NY*NX)
#define TS 172          // smem tile row stride (words)
#define SPLIT 8
#define RPP 22          // pooled-position rows per part (last part gets 15)
#define NBLK (NC*SPLIT)

// scratch (static device arrays; no runtime allocation)
__device__ float g_pla[NC*PH*PW];      // pooled labels  (~12.2 MB)
__device__ float g_ppr[NC*PH*PW];      // pooled probs   (~12.2 MB)
__device__ float g_part[NBLK*192];     // per-block Gram partials (171 tri + 18 sums)
__device__ double g_rmi[NC];

// ---------------------------------------------------------------------------
// Kernel 1: mask + sigmoid + 3x3/stride3 max-pool (pad 1), fused.
// pooled_la = max(targets*mask); pooled_pr = sigmoid(max over masked cls)+1e-6
// ---------------------------------------------------------------------------
__global__ void pool_kernel(const float* __restrict__ cls,
                            const float* __restrict__ tgt,
                            const float* __restrict__ valid)
{
    int nc  = blockIdx.y;
    int idx = blockIdx.x * blockDim.x + threadIdx.x;
    if (idx >= PH*PW) return;
    int py = idx / PW, px = idx % PW;
    int n  = nc / CC;

    const float* vb = valid + (size_t)n  * HH * WW;
    const float* tb = tgt   + (size_t)nc * HH * WW;
    const float* cb = cls   + (size_t)nc * HH * WW;

    int r0 = 3*py - 1, c0 = 3*px - 1;
    float mla = 0.0f;
    float mx  = -3.0e38f;
    int   any = 0;

    #pragma unroll
    for (int dr = 0; dr < 3; dr++) {
        int r = r0 + dr;
        if ((unsigned)r >= (unsigned)HH) continue;
        #pragma unroll
        for (int dc = 0; dc < 3; dc++) {
            int c = c0 + dc;
            if ((unsigned)c >= (unsigned)WW) continue;
            int o = r * WW + c;
            float m = vb[o];
            float t = tb[o] * m;
            mla = fmaxf(mla, t);
            float x = cb[o];
            if (m > 0.0f) { any = 1; mx = fmaxf(mx, x); }
        }
    }
    float pp = (any ? 1.0f / (1.0f + expf(-mx)) : 0.0f) + 1e-6f;
    g_pla[(size_t)nc * (PH*PW) + idx] = mla;
    g_ppr[(size_t)nc * (PH*PW) + idx] = pp;
}

// ---------------------------------------------------------------------------
// Kernel 2: Gram pass.  Z = [la_0..la_8, pr_0..pr_8] (18 x M per (n,c)).
// Computes symmetric Z*Z^T (171 entries) + 18 row sums, split over
// SPLIT row-parts per (n,c).  Warp pairs split the triangle (86 / 85).
// ---------------------------------------------------------------------------
template<int HALF>
__device__ __forceinline__ void accum_body(const float z[18], float acc[86], float ssum[9])
{
    int k = 0;
    #pragma unroll
    for (int i = 0; i < 18; i++) {
        if (HALF == 0) { if (i < 9)  ssum[i]   += z[i]; }
        else           { if (i >= 9) ssum[i-9] += z[i]; }
        #pragma unroll
        for (int j = i; j < 18; j++) {
            if (HALF == 0) { if (k <  86) acc[k]      += z[i] * z[j]; }
            else           { if (k >= 86) acc[k - 86] += z[i] * z[j]; }
            k++;
        }
    }
}

template<int HALF>
__device__ __forceinline__ void gram_loop(const float* sLa, const float* sPr,
                                          int pstart, int total,
                                          float acc[86], float ssum[9])
{
    for (int p = pstart; p < total; p += 128) {
        int y = p / NX, x = p - y * NX;
        float z[18];
        #pragma unroll
        for (int dy = 0; dy < 3; dy++) {
            int ro = (y + dy) * TS + x;
            #pragma unroll
            for (int dx = 0; dx < 3; dx++) {
                z[dy*3 + dx]     = sLa[ro + dx];
                z[9 + dy*3 + dx] = sPr[ro + dx];
            }
        }
        accum_body<HALF>(z, acc, ssum);
    }
}

__global__ __launch_bounds__(256, 1) void gram_kernel()
{
    int b    = blockIdx.x;
    int nc   = b >> 3;
    int part = b & 7;
    int y0   = part * RPP;
    int nyp  = min(RPP, NY - y0);
    int rows = nyp + 2;

    __shared__ float sLa[(RPP+2)*TS];
    __shared__ float sPr[(RPP+2)*TS];

    const float* pla = g_pla + (size_t)nc * (PH*PW) + y0 * PW;
    const float* ppr = g_ppr + (size_t)nc * (PH*PW) + y0 * PW;
    for (int i = threadIdx.x; i < rows * PW; i += 256) {
        int rr = i / PW, cx = i - rr * PW;
        sLa[rr*TS + cx] = pla[i];
        sPr[rr*TS + cx] = ppr[i];
    }
    __syncthreads();

    int warp  = threadIdx.x >> 5;
    int lane  = threadIdx.x & 31;
    int pairI = warp >> 1;
    int half  = warp & 1;
    int total = nyp * NX;

    float acc[86];
    float ssum[9];
    #pragma unroll
    for (int k = 0; k < 86; k++) acc[k] = 0.0f;
    #pragma unroll
    for (int k = 0; k < 9;  k++) ssum[k] = 0.0f;

    int pstart = pairI * 32 + lane;
    if (half == 0) gram_loop<0>(sLa, sPr, pstart, total, acc, ssum);
    else           gram_loop<1>(sLa, sPr, pstart, total, acc, ssum);

    // warp butterfly reduce
    #pragma unroll
    for (int k = 0; k < 86; k++) {
        float v = acc[k];
        #pragma unroll
        for (int o = 16; o; o >>= 1) v += __shfl_xor_sync(0xffffffffu, v, o);
        acc[k] = v;
    }
    #pragma unroll
    for (int k = 0; k < 9; k++) {
        float v = ssum[k];
        #pragma unroll
        for (int o = 16; o; o >>= 1) v += __shfl_xor_sync(0xffffffffu, v, o);
        ssum[k] = v;
    }

    __syncthreads();                  // tiles no longer needed; reuse sLa
    float* red = sLa;
    if (threadIdx.x < 192) red[threadIdx.x] = 0.0f;
    __syncthreads();
    if (lane == 0) {
        int base = half ? 86 : 0;
        int cnt  = half ? 85 : 86;
        for (int k = 0; k < cnt; k++) atomicAdd(&red[base + k], acc[k]);
        for (int k = 0; k < 9;  k++) atomicAdd(&red[171 + half*9 + k], ssum[k]);
    }
    __syncthreads();
    if (threadIdx.x < 189) g_part[(size_t)b * 192 + threadIdx.x] = red[threadIdx.x];
}

// ---------------------------------------------------------------------------
// Kernel 3: per-(n,c) 9x9 solve in fp64.
// appro = la_cov - cross (pr_cov+aI)^-1 cross^T, via Cholesky; rmi = sum log(diag chol + 1e-8)
// ---------------------------------------------------------------------------
__device__ __forceinline__ int tri_idx(int i, int j)  // i <= j
{
    return i*18 - (i*(i-1))/2 + (j - i);
}

__global__ void solve_kernel()
{
    int t = blockIdx.x;   // 0..103, blockDim = 1

    float Gs[189];
    for (int k = 0; k < 189; k++) {
        float a = 0.0f;
        for (int p = 0; p < SPLIT; p++)
            a += g_part[(size_t)(t*SPLIT + p) * 192 + k];
        Gs[k] = a;
    }

    double s[18];
    for (int i = 0; i < 18; i++) s[i] = (double)Gs[171 + i];
    const double invM = 1.0 / (double)MTOT;

    double A[9][9], la[9][9], Wm[9][9];
    for (int d = 0; d < 9; d++) {
        for (int e = 0; e < 9; e++) {
            int i, j;
            // pr_cov + ridge
            i = 9 + d; j = 9 + e; if (i > j) { int tmp=i; i=j; j=tmp; }
            A[d][e]  = (double)Gs[tri_idx(i, j)] - s[9+d]*s[9+e]*invM + (d == e ? 1e-3 : 0.0);
            // la_cov
            i = d; j = e; if (i > j) { int tmp=i; i=j; j=tmp; }
            la[d][e] = (double)Gs[tri_idx(i, j)] - s[d]*s[e]*invM;
            // Wm initialized to cross^T:  Wm[f][e] = cross[e][f] = la_e . pr_f (centered)
            Wm[d][e] = (double)Gs[tri_idx(e, 9 + d)] - s[e]*s[9+d]*invM;
        }
    }

    // Cholesky of A (lower, in place)
    for (int j = 0; j < 9; j++) {
        double dd = A[j][j];
        for (int k = 0; k < j; k++) dd -= A[j][k]*A[j][k];
        dd = sqrt(fmax(dd, 1e-300));
        A[j][j] = dd;
        double inv = 1.0 / dd;
        for (int i = j+1; i < 9; i++) {
            double v = A[i][j];
            for (int k = 0; k < j; k++) v -= A[i][k]*A[j][k];
            A[i][j] = v * inv;
        }
    }
    // Forward solve L * W = cross^T (in place on Wm)
    for (int f = 0; f < 9; f++) {
        double inv = 1.0 / A[f][f];
        for (int e = 0; e < 9; e++) {
            double v = Wm[f][e];
            for (int k = 0; k < f; k++) v -= A[f][k]*Wm[k][e];
            Wm[f][e] = v * inv;
        }
    }
    // appro = la - W^T W + ridge; Cholesky; logdet
    double B[9][9];
    for (int d = 0; d < 9; d++)
        for (int g = 0; g < 9; g++) {
            double v = la[d][g];
            for (int f = 0; f < 9; f++) v -= Wm[f][d]*Wm[f][g];
            B[d][g] = v + (d == g ? 1e-3 : 0.0);
        }
    double rmi = 0.0;
    for (int j = 0; j < 9; j++) {
        double dd = B[j][j];
        for (int k = 0; k < j; k++) dd -= B[j][k]*B[j][k];
        dd = sqrt(fmax(dd, 1e-300));
        B[j][j] = dd;
        double inv = 1.0 / dd;
        for (int i = j+1; i < 9; i++) {
            double v = B[i][j];
            for (int k = 0; k < j; k++) v -= B[i][k]*B[j][k];
            B[i][j] = v * inv;
        }
        rmi += log(dd + 1e-8);
    }
    g_rmi[t] = rmi;   // == 0.5 * logdet
}

// ---------------------------------------------------------------------------
// Kernel 4: deterministic final reduction.  out = sum(rmi)/ (N * HALF_D)
// ---------------------------------------------------------------------------
__global__ void reduce_kernel(float* out)
{
    double a = 0.0;
    for (int i = 0; i < NC; i++) a += g_rmi[i];
    out[0] = (float)(a / 36.0);   // /4 (mean over n) /9 (HALF_D)
}

// ---------------------------------------------------------------------------
extern "C" void kernel_launch(void* const* d_in, const int* in_sizes, int n_in,
                              void* d_out, int out_size)
{
    const float* cls   = (const float*)d_in[0];
    const float* tgt   = (const float*)d_in[1];
    const float* valid = (const float*)d_in[2];

    dim3 pg((PH*PW + 255) / 256, NC);
    pool_kernel<<<pg, 256>>>(cls, tgt, valid);
    gram_kernel<<<NBLK, 256>>>();
    solve_kernel<<<NC, 1>>>();
    reduce_kernel<<<1, 1>>>((float*)d_out);
}

// round 4
// speedup vs baseline: 1.7256x; 1.7256x over previous
#include <cuda_runtime.h>
#include <math.h>

#define NN 4
#define CC 26
#define NC 104
#define HH 512
#define WW 512
#define PH 171
#define PW 171
#define NY 169
#define NX 169
#define MTOT (NY*NX)
#define TS 172          // smem tile row stride (words)
#define SPLIT 8
#define RPP 22          // pooled-position rows per part (last part gets 15)
#define NBLK (NC*SPLIT)

typedef unsigned long long ull;

// scratch (static device arrays; no runtime allocation)
__device__ float g_pla[NC*PH*PW];      // pooled labels  (~12.2 MB)
__device__ float g_ppr[NC*PH*PW];      // pooled probs   (~12.2 MB)
__device__ float g_part[NBLK*192];     // per-block Gram partials (171 tri + 18 sums)
__device__ double g_rmi[NC];

// ---- f32x2 packed helpers (sm_103a FFMA2 via PTX) -------------------------
__device__ __forceinline__ ull pk2(float lo, float hi) {
    ull r; asm("mov.b64 %0,{%1,%2};" : "=l"(r) : "f"(lo), "f"(hi)); return r;
}
__device__ __forceinline__ void fma2(ull& acc, ull a, ull b) {
    asm("fma.rn.f32x2 %0,%1,%2,%0;" : "+l"(acc) : "l"(a), "l"(b));
}
__device__ __forceinline__ void add2(ull& acc, ull v) {
    asm("add.rn.f32x2 %0,%1,%0;" : "+l"(acc) : "l"(v));
}
__device__ __forceinline__ void upk2(ull v, float& lo, float& hi) {
    asm("mov.b64 {%0,%1},%2;" : "=f"(lo), "=f"(hi) : "l"(v));
}
__device__ __forceinline__ int tri_idx(int i, int j)  // i <= j, 18x18 upper tri
{
    return i*18 - (i*(i-1))/2 + (j - i);
}

// ---------------------------------------------------------------------------
// Kernel 1: mask + sigmoid + 3x3/stride3 max-pool (pad 1), fused.
// ---------------------------------------------------------------------------
__global__ void pool_kernel(const float* __restrict__ cls,
                            const float* __restrict__ tgt,
                            const float* __restrict__ valid)
{
    int nc  = blockIdx.y;
    int idx = blockIdx.x * blockDim.x + threadIdx.x;
    if (idx >= PH*PW) return;
    int py = idx / PW, px = idx % PW;
    int n  = nc / CC;

    const float* vb = valid + (size_t)n  * HH * WW;
    const float* tb = tgt   + (size_t)nc * HH * WW;
    const float* cb = cls   + (size_t)nc * HH * WW;

    int r0 = 3*py - 1, c0 = 3*px - 1;
    float mla = 0.0f;
    float mx  = -3.0e38f;
    int   any = 0;

    #pragma unroll
    for (int dr = 0; dr < 3; dr++) {
        int r = r0 + dr;
        if ((unsigned)r >= (unsigned)HH) continue;
        #pragma unroll
        for (int dc = 0; dc < 3; dc++) {
            int c = c0 + dc;
            if ((unsigned)c >= (unsigned)WW) continue;
            int o = r * WW + c;
            float m = vb[o];
            float t = tb[o] * m;
            mla = fmaxf(mla, t);
            float x = cb[o];
            if (m > 0.0f) { any = 1; mx = fmaxf(mx, x); }
        }
    }
    float pp = (any ? 1.0f / (1.0f + expf(-mx)) : 0.0f) + 1e-6f;
    g_pla[(size_t)nc * (PH*PW) + idx] = mla;
    g_ppr[(size_t)nc * (PH*PW) + idx] = pp;
}

// ---------------------------------------------------------------------------
// Kernel 2: Gram pass with packed f32x2 FFMA.
// Z = [la_0..la_8, pr_0..pr_8] (18 x M per (n,c)); 171-entry triangle packed
// into 81 f32x2 FFMAs + 9 scalar diagonals (odd i). Split across warp pairs.
// ---------------------------------------------------------------------------
#define NP0 41
#define NP1 40

template<int HALF>
__device__ __forceinline__ void accum_body(const float z[18],
                                           ull pacc[HALF ? NP1 : NP0],
                                           float sdiag[5], float ssum[9])
{
    ull bc[18], pj[9];
    #pragma unroll
    for (int i = 0; i < 18; i++) bc[i] = pk2(z[i], z[i]);
    #pragma unroll
    for (int m = 0; m < 9; m++) pj[m] = pk2(z[2*m], z[2*m+1]);

    #pragma unroll
    for (int i = 0; i < 9; i++) {
        if (HALF == 0) ssum[i] += z[i];
        else           ssum[i] += z[9 + i];
    }

    int pc = 0, sc = 0;
    #pragma unroll
    for (int i = 0; i < 18; i++) {
        if (i & 1) {
            if (HALF == 0) { if (sc < 5)  sdiag[sc]     += z[i]*z[i]; }
            else           { if (sc >= 5) sdiag[sc - 5] += z[i]*z[i]; }
            sc++;
        }
        #pragma unroll
        for (int m = (i + 1) >> 1; m < 9; m++) {
            if (HALF == 0) { if (pc <  NP0) fma2(pacc[pc],       bc[i], pj[m]); }
            else           { if (pc >= NP0) fma2(pacc[pc - NP0], bc[i], pj[m]); }
            pc++;
        }
    }
}

template<int HALF>
__device__ __forceinline__ void gram_half(const float* sLa, const float* sPr,
                                          int pstart, int total,
                                          int lane, float* red)
{
    const int NP = HALF ? NP1 : NP0;
    ull   pacc[HALF ? NP1 : NP0];
    float sdiag[5];
    float ssum[9];
    #pragma unroll
    for (int k = 0; k < NP; k++) pacc[k] = 0ull;
    #pragma unroll
    for (int k = 0; k < 5; k++) sdiag[k] = 0.0f;
    #pragma unroll
    for (int k = 0; k < 9; k++) ssum[k] = 0.0f;

    for (int p = pstart; p < total; p += 128) {
        int y = p / NX, x = p - y * NX;
        float z[18];
        #pragma unroll
        for (int dy = 0; dy < 3; dy++) {
            int ro = (y + dy) * TS + x;
            #pragma unroll
            for (int dx = 0; dx < 3; dx++) {
                z[dy*3 + dx]     = sLa[ro + dx];
                z[9 + dy*3 + dx] = sPr[ro + dx];
            }
        }
        accum_body<HALF>(z, pacc, sdiag, ssum);
    }

    // warp butterfly reduce
    #pragma unroll
    for (int k = 0; k < NP; k++) {
        ull v = pacc[k];
        #pragma unroll
        for (int o = 16; o; o >>= 1) { ull w = __shfl_xor_sync(0xffffffffu, v, o); add2(v, w); }
        pacc[k] = v;
    }
    #pragma unroll
    for (int k = 0; k < 5; k++) {
        float v = sdiag[k];
        #pragma unroll
        for (int o = 16; o; o >>= 1) v += __shfl_xor_sync(0xffffffffu, v, o);
        sdiag[k] = v;
    }
    #pragma unroll
    for (int k = 0; k < 9; k++) {
        float v = ssum[k];
        #pragma unroll
        for (int o = 16; o; o >>= 1) v += __shfl_xor_sync(0xffffffffu, v, o);
        ssum[k] = v;
    }

    if (lane == 0) {
        int pc = 0, sc = 0;
        #pragma unroll
        for (int i = 0; i < 18; i++) {
            if (i & 1) {
                bool own = (HALF == 0) ? (sc < 5) : (sc >= 5);
                if (own) atomicAdd(&red[tri_idx(i, i)], sdiag[(HALF == 0) ? sc : sc - 5]);
                sc++;
            }
            #pragma unroll
            for (int m = (i + 1) >> 1; m < 9; m++) {
                bool own = (HALF == 0) ? (pc < NP0) : (pc >= NP0);
                if (own) {
                    float lo, hi;
                    upk2(pacc[(HALF == 0) ? pc : pc - NP0], lo, hi);
                    atomicAdd(&red[tri_idx(i, 2*m)],     lo);
                    atomicAdd(&red[tri_idx(i, 2*m + 1)], hi);
                }
                pc++;
            }
        }
        #pragma unroll
        for (int k = 0; k < 9; k++)
            atomicAdd(&red[171 + HALF*9 + k], ssum[k]);
    }
}

__global__ __launch_bounds__(256, 1) void gram_kernel()
{
    int b    = blockIdx.x;
    int nc   = b >> 3;
    int part = b & 7;
    int y0   = part * RPP;
    int nyp  = min(RPP, NY - y0);
    int rows = nyp + 2;

    __shared__ float sLa[(RPP+2)*TS];
    __shared__ float sPr[(RPP+2)*TS];

    const float* pla = g_pla + (size_t)nc * (PH*PW) + y0 * PW;
    const float* ppr = g_ppr + (size_t)nc * (PH*PW) + y0 * PW;
    for (int i = threadIdx.x; i < rows * PW; i += 256) {
        int rr = i / PW, cx = i - rr * PW;
        sLa[rr*TS + cx] = pla[i];
        sPr[rr*TS + cx] = ppr[i];
    }
    __syncthreads();

    __shared__ float red[192];
    if (threadIdx.x < 192) red[threadIdx.x] = 0.0f;
    __syncthreads();

    int warp  = threadIdx.x >> 5;
    int lane  = threadIdx.x & 31;
    int pairI = warp >> 1;
    int half  = warp & 1;
    int total = nyp * NX;
    int pstart = pairI * 32 + lane;

    if (half == 0) gram_half<0>(sLa, sPr, pstart, total, lane, red);
    else           gram_half<1>(sLa, sPr, pstart, total, lane, red);

    __syncthreads();
    if (threadIdx.x < 189) g_part[(size_t)b * 192 + threadIdx.x] = red[threadIdx.x];
}

// ---------------------------------------------------------------------------
// Kernel 3: per-(n,c) 9x9 solve in fp64, block-parallel (192 threads).
// ---------------------------------------------------------------------------
__global__ __launch_bounds__(192) void solve_kernel()
{
    __shared__ float  red[192];
    __shared__ double A[81], La[81], W[81], Bm[81], sv[18];

    int t = threadIdx.x, b = blockIdx.x;

    float a = 0.0f;
    if (t < 189) {
        #pragma unroll
        for (int p = 0; p < SPLIT; p++)
            a += g_part[(size_t)(b*SPLIT + p) * 192 + t];
    }
    red[t] = a;
    __syncthreads();
    if (t < 18) sv[t] = (double)red[171 + t];
    __syncthreads();

    const double invM = 1.0 / (double)MTOT;
    if (t < 81) {
        int d = t / 9, e = t % 9;
        int i, j;
        // pr_cov + ridge
        i = 9 + d; j = 9 + e; if (i > j) { int q = i; i = j; j = q; }
        A[t]  = (double)red[tri_idx(i, j)] - sv[9+d]*sv[9+e]*invM + (d == e ? 1e-3 : 0.0);
        // la_cov
        i = d; j = e; if (i > j) { int q = i; i = j; j = q; }
        La[t] = (double)red[tri_idx(i, j)] - sv[d]*sv[e]*invM;
        // W[d*9+e] = cross^T[d][e] = la_e . pr_d   (e <= 9+d always)
        W[t]  = (double)red[tri_idx(e, 9 + d)] - sv[e]*sv[9+d]*invM;
    }
    __syncthreads();

    if (t < 32) {
        // Cholesky of A (lower, in place), warp-parallel rows
        #pragma unroll 1
        for (int j = 0; j < 9; j++) {
            if (t == 0) {
                double dd = A[j*9 + j];
                for (int k = 0; k < j; k++) dd -= A[j*9 + k]*A[j*9 + k];
                A[j*9 + j] = sqrt(fmax(dd, 1e-300));
            }
            __syncwarp();
            if (t > j && t < 9) {
                double v = A[t*9 + j];
                for (int k = 0; k < j; k++) v -= A[t*9 + k]*A[j*9 + k];
                A[t*9 + j] = v / A[j*9 + j];
            }
            __syncwarp();
        }
        // Forward solve L * W = cross^T (in place), columns parallel
        #pragma unroll 1
        for (int f = 0; f < 9; f++) {
            if (t < 9) {
                double v = W[f*9 + t];
                for (int k = 0; k < f; k++) v -= A[f*9 + k]*W[k*9 + t];
                W[f*9 + t] = v / A[f*9 + f];
            }
            __syncwarp();
        }
    }
    __syncthreads();

    if (t < 81) {
        int d = t / 9, g = t % 9;
        double v = La[t];
        #pragma unroll
        for (int f = 0; f < 9; f++) v -= W[f*9 + d]*W[f*9 + g];
        Bm[t] = v + (d == g ? 1e-3 : 0.0);
    }
    __syncthreads();

    if (t < 32) {
        #pragma unroll 1
        for (int j = 0; j < 9; j++) {
            if (t == 0) {
                double dd = Bm[j*9 + j];
                for (int k = 0; k < j; k++) dd -= Bm[j*9 + k]*Bm[j*9 + k];
                Bm[j*9 + j] = sqrt(fmax(dd, 1e-300));
            }
            __syncwarp();
            if (t > j && t < 9) {
                double v = Bm[t*9 + j];
                for (int k = 0; k < j; k++) v -= Bm[t*9 + k]*Bm[j*9 + k];
                Bm[t*9 + j] = v / Bm[j*9 + j];
            }
            __syncwarp();
        }
        if (t == 0) {
            double r = 0.0;
            for (int j = 0; j < 9; j++) r += log(Bm[j*9 + j] + 1e-8);
            g_rmi[b] = r;   // == 0.5 * logdet
        }
    }
}

// ---------------------------------------------------------------------------
// Kernel 4: deterministic tree reduction.  out = sum(rmi) / 36
// ---------------------------------------------------------------------------
__global__ void reduce_kernel(float* out)
{
    __shared__ double sm[128];
    int t = threadIdx.x;
    sm[t] = (t < NC) ? g_rmi[t] : 0.0;
    __syncthreads();
    #pragma unroll
    for (int s = 64; s; s >>= 1) {
        if (t < s) sm[t] += sm[t + s];
        __syncthreads();
    }
    if (t == 0) out[0] = (float)(sm[0] / 36.0);
}

// ---------------------------------------------------------------------------
extern "C" void kernel_launch(void* const* d_in, const int* in_sizes, int n_in,
                              void* d_out, int out_size)
{
    const float* cls   = (const float*)d_in[0];
    const float* tgt   = (const float*)d_in[1];
    const float* valid = (const float*)d_in[2];

    dim3 pg((PH*PW + 255) / 256, NC);
    pool_kernel<<<pg, 256>>>(cls, tgt, valid);
    gram_kernel<<<NBLK, 256>>>();
    solve_kernel<<<NC, 192>>>();
    reduce_kernel<<<1, 128>>>((float*)d_out);
}

// round 5
// speedup vs baseline: 1.7679x; 1.0245x over previous
#include <cuda_runtime.h>
#include <math.h>

#define NN 4
#define CC 26
#define NC 104
#define HH 512
#define WW 512
#define PH 171
#define PW 171
#define NY 169
#define NX 169
#define MTOT (NY*NX)
#define TS 172          // gram smem tile row stride (words)
#define SPLIT 8
#define RPP 22          // pooled-position rows per part (last part gets 15)
#define NBLK (NC*SPLIT)
#define PRB 2           // pool: output rows per block
#define RSTR 520        // pool: smem row stride (4 pad + 512 + 4)

typedef unsigned long long ull;

// scratch (static device arrays; no runtime allocation)
__device__ float g_pla[NC*PH*PW];      // pooled labels  (~12.2 MB)
__device__ float g_ppr[NC*PH*PW];      // pooled probs   (~12.2 MB)
__device__ float g_part[NBLK*192];     // per-block Gram partials (171 tri + 18 sums)
__device__ double g_rmi[NC];
__device__ int    g_cnt = 0;

// ---- f32x2 packed helpers (sm_103a FFMA2 via PTX) -------------------------
__device__ __forceinline__ ull pk2(float lo, float hi) {
    ull r; asm("mov.b64 %0,{%1,%2};" : "=l"(r) : "f"(lo), "f"(hi)); return r;
}
__device__ __forceinline__ void fma2(ull& acc, ull a, ull b) {
    asm("fma.rn.f32x2 %0,%1,%2,%0;" : "+l"(acc) : "l"(a), "l"(b));
}
__device__ __forceinline__ void add2(ull& acc, ull v) {
    asm("add.rn.f32x2 %0,%1,%0;" : "+l"(acc) : "l"(v));
}
__device__ __forceinline__ void upk2(ull v, float& lo, float& hi) {
    asm("mov.b64 {%0,%1},%2;" : "=f"(lo), "=f"(hi) : "l"(v));
}
__device__ __forceinline__ int tri_idx(int i, int j)  // i <= j, 18x18 upper tri
{
    return i*18 - (i*(i-1))/2 + (j - i);
}

// ---------------------------------------------------------------------------
// Kernel 1 (v2): mask + sigmoid + 3x3/stride3 max-pool, smem-staged.
// Windows are stride-3 disjoint -> each input element read exactly once.
// Load phase (coalesced float4) fuses the masking:
//   sT = tgt*m          (label plane; >=0, pad 0 is neutral)
//   sX = m>0 ? x : -BIG (pre-sigmoid plane; pad -BIG neutral; all-masked ->
//                        sigmoid(-BIG)=0 -> +1e-6 matches reference)
// ---------------------------------------------------------------------------
__global__ __launch_bounds__(256) void pool_kernel(const float* __restrict__ cls,
                                                   const float* __restrict__ tgt,
                                                   const float* __restrict__ valid)
{
    int nc  = blockIdx.y;
    int n   = nc / CC;
    int py0 = blockIdx.x * PRB;
    int t   = threadIdx.x;

    __shared__ float sT[6*RSTR];
    __shared__ float sX[6*RSTR];

    const float* cb = cls   + (size_t)nc * HH * WW;
    const float* tb = tgt   + (size_t)nc * HH * WW;
    const float* vb = valid + (size_t)n  * HH * WW;

    const float BIG = -3.0e38f;

    for (int q = t; q < 6*128; q += 256) {
        int i = q >> 7;          // smem row 0..5
        int k = q & 127;         // float4 index within row
        int r = 3*py0 - 1 + i;   // input row
        float4 T4, X4;
        if ((unsigned)r < (unsigned)HH) {
            float4 c = ((const float4*)(cb + (size_t)r*WW))[k];
            float4 g = ((const float4*)(tb + (size_t)r*WW))[k];
            float4 v = ((const float4*)(vb + (size_t)r*WW))[k];
            T4.x = g.x*v.x; T4.y = g.y*v.y; T4.z = g.z*v.z; T4.w = g.w*v.w;
            X4.x = v.x > 0.0f ? c.x : BIG;
            X4.y = v.y > 0.0f ? c.y : BIG;
            X4.z = v.z > 0.0f ? c.z : BIG;
            X4.w = v.w > 0.0f ? c.w : BIG;
        } else {
            T4.x = T4.y = T4.z = T4.w = 0.0f;
            X4.x = X4.y = X4.z = X4.w = BIG;
        }
        *(float4*)&sT[i*RSTR + 4 + 4*k] = T4;
        *(float4*)&sX[i*RSTR + 4 + 4*k] = X4;
    }
    if (t < 6) { sT[t*RSTR + 3] = 0.0f; sX[t*RSTR + 3] = BIG; }  // col -1 pad
    __syncthreads();

    for (int o = t; o < PRB*PW; o += 256) {
        int pyl = o / PW, px = o - pyl*PW;
        int py  = py0 + pyl;
        if (py >= PH) continue;
        int base = pyl*3*RSTR + 3 + 3*px;     // col index of (px, dc=-1)
        float mla = 0.0f, mx = BIG;
        #pragma unroll
        for (int rr = 0; rr < 3; rr++) {
            int bb = base + rr*RSTR;
            #pragma unroll
            for (int cc = 0; cc < 3; cc++) {
                mla = fmaxf(mla, sT[bb + cc]);
                mx  = fmaxf(mx,  sX[bb + cc]);
            }
        }
        float pp = 1.0f/(1.0f + __expf(-mx)) + 1e-6f;
        size_t ob = (size_t)nc * (PH*PW) + (size_t)py*PW + px;
        g_pla[ob] = mla;
        g_ppr[ob] = pp;
    }
}

// ---------------------------------------------------------------------------
// Kernel 2: Gram pass with packed f32x2 FFMA.
// Z = [la_0..la_8, pr_0..pr_8] (18 x M per (n,c)); 171-entry triangle packed
// into 81 f32x2 FFMAs + 9 scalar diagonals (odd i). Split across warp pairs.
// ---------------------------------------------------------------------------
#define NP0 41
#define NP1 40

template<int HALF>
__device__ __forceinline__ void accum_body(const float z[18],
                                           ull pacc[HALF ? NP1 : NP0],
                                           float sdiag[5], float ssum[9])
{
    ull bc[18], pj[9];
    #pragma unroll
    for (int i = 0; i < 18; i++) bc[i] = pk2(z[i], z[i]);
    #pragma unroll
    for (int m = 0; m < 9; m++) pj[m] = pk2(z[2*m], z[2*m+1]);

    #pragma unroll
    for (int i = 0; i < 9; i++) {
        if (HALF == 0) ssum[i] += z[i];
        else           ssum[i] += z[9 + i];
    }

    int pc = 0, sc = 0;
    #pragma unroll
    for (int i = 0; i < 18; i++) {
        if (i & 1) {
            if (HALF == 0) { if (sc < 5)  sdiag[sc]     += z[i]*z[i]; }
            else           { if (sc >= 5) sdiag[sc - 5] += z[i]*z[i]; }
            sc++;
        }
        #pragma unroll
        for (int m = (i + 1) >> 1; m < 9; m++) {
            if (HALF == 0) { if (pc <  NP0) fma2(pacc[pc],       bc[i], pj[m]); }
            else           { if (pc >= NP0) fma2(pacc[pc - NP0], bc[i], pj[m]); }
            pc++;
        }
    }
}

template<int HALF>
__device__ __forceinline__ void gram_half(const float* sLa, const float* sPr,
                                          int pstart, int total,
                                          int lane, float* red)
{
    const int NP = HALF ? NP1 : NP0;
    ull   pacc[HALF ? NP1 : NP0];
    float sdiag[5];
    float ssum[9];
    #pragma unroll
    for (int k = 0; k < NP; k++) pacc[k] = 0ull;
    #pragma unroll
    for (int k = 0; k < 5; k++) sdiag[k] = 0.0f;
    #pragma unroll
    for (int k = 0; k < 9; k++) ssum[k] = 0.0f;

    for (int p = pstart; p < total; p += 128) {
        int y = p / NX, x = p - y * NX;
        float z[18];
        #pragma unroll
        for (int dy = 0; dy < 3; dy++) {
            int ro = (y + dy) * TS + x;
            #pragma unroll
            for (int dx = 0; dx < 3; dx++) {
                z[dy*3 + dx]     = sLa[ro + dx];
                z[9 + dy*3 + dx] = sPr[ro + dx];
            }
        }
        accum_body<HALF>(z, pacc, sdiag, ssum);
    }

    // warp butterfly reduce
    #pragma unroll
    for (int k = 0; k < NP; k++) {
        ull v = pacc[k];
        #pragma unroll
        for (int o = 16; o; o >>= 1) { ull w = __shfl_xor_sync(0xffffffffu, v, o); add2(v, w); }
        pacc[k] = v;
    }
    #pragma unroll
    for (int k = 0; k < 5; k++) {
        float v = sdiag[k];
        #pragma unroll
        for (int o = 16; o; o >>= 1) v += __shfl_xor_sync(0xffffffffu, v, o);
        sdiag[k] = v;
    }
    #pragma unroll
    for (int k = 0; k < 9; k++) {
        float v = ssum[k];
        #pragma unroll
        for (int o = 16; o; o >>= 1) v += __shfl_xor_sync(0xffffffffu, v, o);
        ssum[k] = v;
    }

    if (lane == 0) {
        int pc = 0, sc = 0;
        #pragma unroll
        for (int i = 0; i < 18; i++) {
            if (i & 1) {
                bool own = (HALF == 0) ? (sc < 5) : (sc >= 5);
                if (own) atomicAdd(&red[tri_idx(i, i)], sdiag[(HALF == 0) ? sc : sc - 5]);
                sc++;
            }
            #pragma unroll
            for (int m = (i + 1) >> 1; m < 9; m++) {
                bool own = (HALF == 0) ? (pc < NP0) : (pc >= NP0);
                if (own) {
                    float lo, hi;
                    upk2(pacc[(HALF == 0) ? pc : pc - NP0], lo, hi);
                    atomicAdd(&red[tri_idx(i, 2*m)],     lo);
                    atomicAdd(&red[tri_idx(i, 2*m + 1)], hi);
                }
                pc++;
            }
        }
        #pragma unroll
        for (int k = 0; k < 9; k++)
            atomicAdd(&red[171 + HALF*9 + k], ssum[k]);
    }
}

__global__ __launch_bounds__(256, 1) void gram_kernel()
{
    int b    = blockIdx.x;
    int nc   = b >> 3;
    int part = b & 7;
    int y0   = part * RPP;
    int nyp  = min(RPP, NY - y0);
    int rows = nyp + 2;

    __shared__ float sLa[(RPP+2)*TS];
    __shared__ float sPr[(RPP+2)*TS];

    const float* pla = g_pla + (size_t)nc * (PH*PW) + y0 * PW;
    const float* ppr = g_ppr + (size_t)nc * (PH*PW) + y0 * PW;
    for (int i = threadIdx.x; i < rows * PW; i += 256) {
        int rr = i / PW, cx = i - rr * PW;
        sLa[rr*TS + cx] = pla[i];
        sPr[rr*TS + cx] = ppr[i];
    }
    __syncthreads();

    __shared__ float red[192];
    if (threadIdx.x < 192) red[threadIdx.x] = 0.0f;
    __syncthreads();

    int warp  = threadIdx.x >> 5;
    int lane  = threadIdx.x & 31;
    int pairI = warp >> 1;
    int half  = warp & 1;
    int total = nyp * NX;
    int pstart = pairI * 32 + lane;

    if (half == 0) gram_half<0>(sLa, sPr, pstart, total, lane, red);
    else           gram_half<1>(sLa, sPr, pstart, total, lane, red);

    __syncthreads();
    if (threadIdx.x < 189) g_part[(size_t)b * 192 + threadIdx.x] = red[threadIdx.x];
}

// ---------------------------------------------------------------------------
// Kernel 3: per-(n,c) 9x9 solve in fp64, block-parallel (192 threads).
// Last block (threadfence + counter) folds the final reduction.
// ---------------------------------------------------------------------------
__global__ __launch_bounds__(192) void solve_kernel(float* __restrict__ out)
{
    __shared__ float  red[192];
    __shared__ double A[81], La[81], W[81], Bm[81], sv[18];
    __shared__ double sm[128];
    __shared__ bool   isLast;

    int t = threadIdx.x, b = blockIdx.x;

    float a = 0.0f;
    if (t < 189) {
        #pragma unroll
        for (int p = 0; p < SPLIT; p++)
            a += g_part[(size_t)(b*SPLIT + p) * 192 + t];
    }
    red[t] = a;
    __syncthreads();
    if (t < 18) sv[t] = (double)red[171 + t];
    __syncthreads();

    const double invM = 1.0 / (double)MTOT;
    if (t < 81) {
        int d = t / 9, e = t % 9;
        int i, j;
        // pr_cov + ridge
        i = 9 + d; j = 9 + e; if (i > j) { int q = i; i = j; j = q; }
        A[t]  = (double)red[tri_idx(i, j)] - sv[9+d]*sv[9+e]*invM + (d == e ? 1e-3 : 0.0);
        // la_cov
        i = d; j = e; if (i > j) { int q = i; i = j; j = q; }
        La[t] = (double)red[tri_idx(i, j)] - sv[d]*sv[e]*invM;
        // W[d*9+e] = cross^T[d][e] = la_e . pr_d
        W[t]  = (double)red[tri_idx(e, 9 + d)] - sv[e]*sv[9+d]*invM;
    }
    __syncthreads();

    if (t < 32) {
        // Cholesky of A (lower, in place), warp-parallel rows
        #pragma unroll 1
        for (int j = 0; j < 9; j++) {
            if (t == 0) {
                double dd = A[j*9 + j];
                for (int k = 0; k < j; k++) dd -= A[j*9 + k]*A[j*9 + k];
                A[j*9 + j] = sqrt(fmax(dd, 1e-300));
            }
            __syncwarp();
            if (t > j && t < 9) {
                double v = A[t*9 + j];
                for (int k = 0; k < j; k++) v -= A[t*9 + k]*A[j*9 + k];
                A[t*9 + j] = v / A[j*9 + j];
            }
            __syncwarp();
        }
        // Forward solve L * W = cross^T (in place), columns parallel
        #pragma unroll 1
        for (int f = 0; f < 9; f++) {
            if (t < 9) {
                double v = W[f*9 + t];
                for (int k = 0; k < f; k++) v -= A[f*9 + k]*W[k*9 + t];
                W[f*9 + t] = v / A[f*9 + f];
            }
            __syncwarp();
        }
    }
    __syncthreads();

    if (t < 81) {
        int d = t / 9, g = t % 9;
        double v = La[t];
        #pragma unroll
        for (int f = 0; f < 9; f++) v -= W[f*9 + d]*W[f*9 + g];
        Bm[t] = v + (d == g ? 1e-3 : 0.0);
    }
    __syncthreads();

    if (t < 32) {
        #pragma unroll 1
        for (int j = 0; j < 9; j++) {
            if (t == 0) {
                double dd = Bm[j*9 + j];
                for (int k = 0; k < j; k++) dd -= Bm[j*9 + k]*Bm[j*9 + k];
                Bm[j*9 + j] = sqrt(fmax(dd, 1e-300));
            }
            __syncwarp();
            if (t > j && t < 9) {
                double v = Bm[t*9 + j];
                for (int k = 0; k < j; k++) v -= Bm[t*9 + k]*Bm[j*9 + k];
                Bm[t*9 + j] = v / Bm[j*9 + j];
            }
            __syncwarp();
        }
        if (t == 0) {
            double r = 0.0;
            for (int j = 0; j < 9; j++) r += log(Bm[j*9 + j] + 1e-8);
            g_rmi[b] = r;   // == 0.5 * logdet
        }
    }
    __syncthreads();

    // last block folds the deterministic final reduction
    if (t == 0) {
        __threadfence();
        int old = atomicAdd(&g_cnt, 1);
        isLast = (old == NC - 1);
    }
    __syncthreads();
    if (isLast) {
        __threadfence();
        if (t < 128) sm[t] = (t < NC) ? g_rmi[t] : 0.0;
        __syncthreads();
        #pragma unroll
        for (int s = 64; s; s >>= 1) {
            if (t < s) sm[t] += sm[t + s];
            __syncthreads();
        }
        if (t == 0) {
            out[0] = (float)(sm[0] / 36.0);   // /4 (mean over n) /9 (HALF_D)
            g_cnt = 0;                        // reset for graph replay
        }
    }
}

// ---------------------------------------------------------------------------
extern "C" void kernel_launch(void* const* d_in, const int* in_sizes, int n_in,
                              void* d_out, int out_size)
{
    const float* cls   = (const float*)d_in[0];
    const float* tgt   = (const float*)d_in[1];
    const float* valid = (const float*)d_in[2];

    dim3 pg((PH + PRB - 1) / PRB, NC);
    pool_kernel<<<pg, 256>>>(cls, tgt, valid);
    gram_kernel<<<NBLK, 256>>>();
    solve_kernel<<<NC, 192>>>((float*)d_out);
}

// round 9
// speedup vs baseline: 1.9641x; 1.1110x over previous
#include <cuda_runtime.h>
#include <math.h>

#define NN 4
#define CC 26
#define NC 104
#define HH 512
#define WW 512
#define PH 171
#define PW 171
#define NY 169
#define NX 169
#define MTOT (NY*NX)
#define TS 172          // gram smem tile row stride (words)
#define SPLIT 8
#define RPP 22          // pooled-position rows per part (last part gets 15)
#define NBLK (NC*SPLIT)
#define GTHR 192        // gram block threads (3 position-groups x 2 halves)
#define PRB 2           // pool: output rows per block
#define RSTR 520        // pool: smem row stride (4 pad + 512 + 4)

typedef unsigned long long ull;

// scratch (static device arrays; no runtime allocation)
__device__ float g_pla[NC*PH*PW];      // pooled labels
__device__ float g_ppr[NC*PH*PW];      // pooled probs
__device__ float g_part[NBLK*192];     // per-block Gram partials (171 tri + 18 sums)
__device__ double g_rmi[NC];
__device__ int    g_cnt = 0;

// ---- f32x2 packed helpers (sm_103a FFMA2 via PTX) -------------------------
__device__ __forceinline__ ull pk2(float lo, float hi) {
    ull r; asm("mov.b64 %0,{%1,%2};" : "=l"(r) : "f"(lo), "f"(hi)); return r;
}
__device__ __forceinline__ void fma2(ull& acc, ull a, ull b) {
    asm("fma.rn.f32x2 %0,%1,%2,%0;" : "+l"(acc) : "l"(a), "l"(b));
}
__device__ __forceinline__ void add2(ull& acc, ull v) {
    asm("add.rn.f32x2 %0,%1,%0;" : "+l"(acc) : "l"(v));
}
__device__ __forceinline__ void upk2(ull v, float& lo, float& hi) {
    asm("mov.b64 {%0,%1},%2;" : "=f"(lo), "=f"(hi) : "l"(v));
}
__device__ __forceinline__ int tri_idx(int i, int j)  // i <= j, 18x18 upper tri
{
    return i*18 - (i*(i-1))/2 + (j - i);
}

// ---------------------------------------------------------------------------
// Kernel 1: mask + sigmoid + 3x3/stride3 max-pool, smem-staged (R5-proven).
// ---------------------------------------------------------------------------
__global__ __launch_bounds__(256) void pool_kernel(const float* __restrict__ cls,
                                                   const float* __restrict__ tgt,
                                                   const float* __restrict__ valid)
{
    int nc  = blockIdx.y;
    int n   = nc / CC;
    int py0 = blockIdx.x * PRB;
    int t   = threadIdx.x;

    __shared__ float sT[6*RSTR];
    __shared__ float sX[6*RSTR];

    const float* cb = cls   + (size_t)nc * HH * WW;
    const float* tb = tgt   + (size_t)nc * HH * WW;
    const float* vb = valid + (size_t)n  * HH * WW;

    const float BIG = -3.0e38f;

    for (int q = t; q < 6*128; q += 256) {
        int i = q >> 7;
        int k = q & 127;
        int r = 3*py0 - 1 + i;
        float4 T4, X4;
        if ((unsigned)r < (unsigned)HH) {
            float4 c = ((const float4*)(cb + (size_t)r*WW))[k];
            float4 g = ((const float4*)(tb + (size_t)r*WW))[k];
            float4 v = ((const float4*)(vb + (size_t)r*WW))[k];
            T4.x = g.x*v.x; T4.y = g.y*v.y; T4.z = g.z*v.z; T4.w = g.w*v.w;
            X4.x = v.x > 0.0f ? c.x : BIG;
            X4.y = v.y > 0.0f ? c.y : BIG;
            X4.z = v.z > 0.0f ? c.z : BIG;
            X4.w = v.w > 0.0f ? c.w : BIG;
        } else {
            T4.x = T4.y = T4.z = T4.w = 0.0f;
            X4.x = X4.y = X4.z = X4.w = BIG;
        }
        *(float4*)&sT[i*RSTR + 4 + 4*k] = T4;
        *(float4*)&sX[i*RSTR + 4 + 4*k] = X4;
    }
    if (t < 6) { sT[t*RSTR + 3] = 0.0f; sX[t*RSTR + 3] = BIG; }
    __syncthreads();

    for (int o = t; o < PRB*PW; o += 256) {
        int pyl = o / PW, px = o - pyl*PW;
        int py  = py0 + pyl;
        if (py >= PH) continue;
        int base = pyl*3*RSTR + 3 + 3*px;
        float mla = 0.0f, mx = BIG;
        #pragma unroll
        for (int rr = 0; rr < 3; rr++) {
            int bb = base + rr*RSTR;
            #pragma unroll
            for (int cc = 0; cc < 3; cc++) {
                mla = fmaxf(mla, sT[bb + cc]);
                mx  = fmaxf(mx,  sX[bb + cc]);
            }
        }
        float pp = 1.0f/(1.0f + __expf(-mx)) + 1e-6f;
        size_t ob = (size_t)nc * (PH*PW) + (size_t)py*PW + px;
        g_pla[ob] = mla;
        g_ppr[ob] = pp;
    }
}

// ---------------------------------------------------------------------------
// Kernel 2: direct Gram pass (R5-proven numerics), packed f32x2 FFMA.
// Z = [la_0..la_8, pr_0..pr_8] (18 x M per (n,c)); 171-entry triangle packed
// into 81 f32x2 FFMAs + 9 scalar diagonals. Warp pairs split the triangle.
// 192 threads (3 position-groups x 2 halves), occupancy 2.
// ---------------------------------------------------------------------------
#define NP0 41
#define NP1 40

template<int HALF>
__device__ __forceinline__ void accum_body(const float z[18],
                                           ull pacc[HALF ? NP1 : NP0],
                                           float sdiag[5], float ssum[9])
{
    ull bc[18], pj[9];
    #pragma unroll
    for (int i = 0; i < 18; i++) bc[i] = pk2(z[i], z[i]);
    #pragma unroll
    for (int m = 0; m < 9; m++) pj[m] = pk2(z[2*m], z[2*m+1]);

    #pragma unroll
    for (int i = 0; i < 9; i++) {
        if (HALF == 0) ssum[i] += z[i];
        else           ssum[i] += z[9 + i];
    }

    int pc = 0, sc = 0;
    #pragma unroll
    for (int i = 0; i < 18; i++) {
        if (i & 1) {
            if (HALF == 0) { if (sc < 5)  sdiag[sc]     += z[i]*z[i]; }
            else           { if (sc >= 5) sdiag[sc - 5] += z[i]*z[i]; }
            sc++;
        }
        #pragma unroll
        for (int m = (i + 1) >> 1; m < 9; m++) {
            if (HALF == 0) { if (pc <  NP0) fma2(pacc[pc],       bc[i], pj[m]); }
            else           { if (pc >= NP0) fma2(pacc[pc - NP0], bc[i], pj[m]); }
            pc++;
        }
    }
}

template<int HALF>
__device__ __forceinline__ void gram_half(const float* sLa, const float* sPr,
                                          int pstart, int total,
                                          int lane, float* red)
{
    const int NP = HALF ? NP1 : NP0;
    ull   pacc[HALF ? NP1 : NP0];
    float sdiag[5];
    float ssum[9];
    #pragma unroll
    for (int k = 0; k < NP; k++) pacc[k] = 0ull;
    #pragma unroll
    for (int k = 0; k < 5; k++) sdiag[k] = 0.0f;
    #pragma unroll
    for (int k = 0; k < 9; k++) ssum[k] = 0.0f;

    for (int p = pstart; p < total; p += 96) {
        int y = p / NX, x = p - y * NX;
        float z[18];
        #pragma unroll
        for (int dy = 0; dy < 3; dy++) {
            int ro = (y + dy) * TS + x;
            #pragma unroll
            for (int dx = 0; dx < 3; dx++) {
                z[dy*3 + dx]     = sLa[ro + dx];
                z[9 + dy*3 + dx] = sPr[ro + dx];
            }
        }
        accum_body<HALF>(z, pacc, sdiag, ssum);
    }

    // warp butterfly reduce
    #pragma unroll
    for (int k = 0; k < NP; k++) {
        ull v = pacc[k];
        #pragma unroll
        for (int o = 16; o; o >>= 1) { ull w = __shfl_xor_sync(0xffffffffu, v, o); add2(v, w); }
        pacc[k] = v;
    }
    #pragma unroll
    for (int k = 0; k < 5; k++) {
        float v = sdiag[k];
        #pragma unroll
        for (int o = 16; o; o >>= 1) v += __shfl_xor_sync(0xffffffffu, v, o);
        sdiag[k] = v;
    }
    #pragma unroll
    for (int k = 0; k < 9; k++) {
        float v = ssum[k];
        #pragma unroll
        for (int o = 16; o; o >>= 1) v += __shfl_xor_sync(0xffffffffu, v, o);
        ssum[k] = v;
    }

    if (lane == 0) {
        int pc = 0, sc = 0;
        #pragma unroll
        for (int i = 0; i < 18; i++) {
            if (i & 1) {
                bool own = (HALF == 0) ? (sc < 5) : (sc >= 5);
                if (own) atomicAdd(&red[tri_idx(i, i)], sdiag[(HALF == 0) ? sc : sc - 5]);
                sc++;
            }
            #pragma unroll
            for (int m = (i + 1) >> 1; m < 9; m++) {
                bool own = (HALF == 0) ? (pc < NP0) : (pc >= NP0);
                if (own) {
                    float lo, hi;
                    upk2(pacc[(HALF == 0) ? pc : pc - NP0], lo, hi);
                    atomicAdd(&red[tri_idx(i, 2*m)],     lo);
                    atomicAdd(&red[tri_idx(i, 2*m + 1)], hi);
                }
                pc++;
            }
        }
        #pragma unroll
        for (int k = 0; k < 9; k++)
            atomicAdd(&red[171 + HALF*9 + k], ssum[k]);
    }
}

__global__ __launch_bounds__(GTHR, 2) void gram_kernel()
{
    int b    = blockIdx.x;
    int nc   = b >> 3;
    int part = b & 7;
    int y0   = part * RPP;
    int nyp  = min(RPP, NY - y0);
    int rows = nyp + 2;

    __shared__ float sLa[(RPP+2)*TS];
    __shared__ float sPr[(RPP+2)*TS];

    const float* pla = g_pla + (size_t)nc * (PH*PW) + y0 * PW;
    const float* ppr = g_ppr + (size_t)nc * (PH*PW) + y0 * PW;
    for (int i = threadIdx.x; i < rows * PW; i += GTHR) {
        int rr = i / PW, cx = i - rr * PW;
        sLa[rr*TS + cx] = pla[i];
        sPr[rr*TS + cx] = ppr[i];
    }
    __syncthreads();

    __shared__ float red[192];
    if (threadIdx.x < 192) red[threadIdx.x] = 0.0f;
    __syncthreads();

    int warp  = threadIdx.x >> 5;
    int lane  = threadIdx.x & 31;
    int pairI = warp >> 1;          // 0..2
    int half  = warp & 1;
    int total = nyp * NX;
    int pstart = pairI * 32 + lane; // stride 96

    if (half == 0) gram_half<0>(sLa, sPr, pstart, total, lane, red);
    else           gram_half<1>(sLa, sPr, pstart, total, lane, red);

    __syncthreads();
    if (threadIdx.x < 189) g_part[(size_t)b * 192 + threadIdx.x] = red[threadIdx.x];
}

// ---------------------------------------------------------------------------
// Kernel 3: per-(n,c) 9x9 solve in fp64, block-parallel (192 threads).
// Last block (threadfence + counter) folds the final reduction.
// ---------------------------------------------------------------------------
__global__ __launch_bounds__(192) void solve_kernel(float* __restrict__ out)
{
    __shared__ float  red[192];
    __shared__ double A[81], La[81], W[81], Bm[81], sv[18];
    __shared__ double sm[128];
    __shared__ bool   isLast;

    int t = threadIdx.x, b = blockIdx.x;

    float a = 0.0f;
    if (t < 189) {
        #pragma unroll
        for (int p = 0; p < SPLIT; p++)
            a += g_part[(size_t)(b*SPLIT + p) * 192 + t];
    }
    red[t] = a;
    __syncthreads();
    if (t < 18) sv[t] = (double)red[171 + t];
    __syncthreads();

    const double invM = 1.0 / (double)MTOT;
    if (t < 81) {
        int d = t / 9, e = t % 9;
        int i, j;
        i = 9 + d; j = 9 + e; if (i > j) { int q = i; i = j; j = q; }
        A[t]  = (double)red[tri_idx(i, j)] - sv[9+d]*sv[9+e]*invM + (d == e ? 1e-3 : 0.0);
        i = d; j = e; if (i > j) { int q = i; i = j; j = q; }
        La[t] = (double)red[tri_idx(i, j)] - sv[d]*sv[e]*invM;
        W[t]  = (double)red[tri_idx(e, 9 + d)] - sv[e]*sv[9+d]*invM;
    }
    __syncthreads();

    if (t < 32) {
        // Cholesky of A (lower, in place), warp-parallel rows
        #pragma unroll 1
        for (int j = 0; j < 9; j++) {
            if (t == 0) {
                double dd = A[j*9 + j];
                for (int k = 0; k < j; k++) dd -= A[j*9 + k]*A[j*9 + k];
                A[j*9 + j] = sqrt(fmax(dd, 1e-300));
            }
            __syncwarp();
            if (t > j && t < 9) {
                double v = A[t*9 + j];
                for (int k = 0; k < j; k++) v -= A[t*9 + k]*A[j*9 + k];
                A[t*9 + j] = v / A[j*9 + j];
            }
            __syncwarp();
        }
        // Forward solve L * W = cross^T (in place), columns parallel
        #pragma unroll 1
        for (int f = 0; f < 9; f++) {
            if (t < 9) {
                double v = W[f*9 + t];
                for (int k = 0; k < f; k++) v -= A[f*9 + k]*W[k*9 + t];
                W[f*9 + t] = v / A[f*9 + f];
            }
            __syncwarp();
        }
    }
    __syncthreads();

    if (t < 81) {
        int d = t / 9, g = t % 9;
        double v = La[t];
        #pragma unroll
        for (int f = 0; f < 9; f++) v -= W[f*9 + d]*W[f*9 + g];
        Bm[t] = v + (d == g ? 1e-3 : 0.0);
    }
    __syncthreads();

    if (t < 32) {
        #pragma unroll 1
        for (int j = 0; j < 9; j++) {
            if (t == 0) {
                double dd = Bm[j*9 + j];
                for (int k = 0; k < j; k++) dd -= Bm[j*9 + k]*Bm[j*9 + k];
                Bm[j*9 + j] = sqrt(fmax(dd, 1e-300));
            }
            __syncwarp();
            if (t > j && t < 9) {
                double v = Bm[t*9 + j];
                for (int k = 0; k < j; k++) v -= Bm[t*9 + k]*Bm[j*9 + k];
                Bm[t*9 + j] = v / Bm[j*9 + j];
            }
            __syncwarp();
        }
        if (t == 0) {
            double r = 0.0;
            for (int j = 0; j < 9; j++) r += log(Bm[j*9 + j] + 1e-8);
            g_rmi[b] = r;   // == 0.5 * logdet
        }
    }
    __syncthreads();

    // last block folds the deterministic final reduction
    if (t == 0) {
        __threadfence();
        int old = atomicAdd(&g_cnt, 1);
        isLast = (old == NC - 1);
    }
    __syncthreads();
    if (isLast) {
        __threadfence();
        if (t < 128) sm[t] = (t < NC) ? g_rmi[t] : 0.0;
        __syncthreads();
        #pragma unroll
        for (int s = 64; s; s >>= 1) {
            if (t < s) sm[t] += sm[t + s];
            __syncthreads();
        }
        if (t == 0) {
            out[0] = (float)(sm[0] / 36.0);   // /4 (mean over n) /9 (HALF_D)
            g_cnt = 0;                        // reset for graph replay
        }
    }
}

// ---------------------------------------------------------------------------
extern "C" void kernel_launch(void* const* d_in, const int* in_sizes, int n_in,
                              void* d_out, int out_size)
{
    const float* cls   = (const float*)d_in[0];
    const float* tgt   = (const float*)d_in[1];
    const float* valid = (const float*)d_in[2];

    dim3 pg((PH + PRB - 1) / PRB, NC);
    pool_kernel<<<pg, 256>>>(cls, tgt, valid);
    gram_kernel<<<NBLK, GTHR>>>();
    solve_kernel<<<NC, 192>>>((float*)d_out);
}